// round 15
// baseline (speedup 1.0000x reference)
#include <cuda_runtime.h>
#include <cuda_bf16.h>
#include <math.h>

typedef unsigned long long ull;

#define SCALE 0.08838834764831843f

// ----------------------------- device scratch -------------------------------
__device__ float  g_qkvp[16 * 32 * 6144];         // k-split partials (QKV)
__device__ float  g_qkv [32 * 6144];              // reduced qkv + bias
__device__ float  g_rqt [48 * 128 * 64];          // roped q, transposed [set][d][hq]
__device__ float  g_knew[2 * 8 * 16 * 128];       // roped new keys
__device__ float  g_vnew[2 * 8 * 16 * 128];       // new values
__device__ float  g_pm [16 * 98 * 64];            // split-K partial max
__device__ float  g_pl [16 * 98 * 64];            // split-K partial sum
__device__ float  g_pacc[16 * 98 * 64 * 128];     // split-K partial accum
__device__ float  g_attn[32 * 4096];              // attention out, tokens x (H*D)
__device__ float  g_op [16 * 32 * 4096];          // k-split partials (O proj)

// ----------------------------- f32x2 helpers --------------------------------
__device__ __forceinline__ ull ffma2(ull a, ull b, ull c) {
    ull d;
    asm("fma.rn.f32x2 %0, %1, %2, %3;" : "=l"(d) : "l"(a), "l"(b), "l"(c));
    return d;
}
__device__ __forceinline__ ull pk2(float x, float y) {
    ull r;
    asm("mov.b64 %0, {%1, %2};" : "=l"(r) : "f"(x), "f"(y));
    return r;
}
__device__ __forceinline__ float2 unpk(ull v) {
    float2 r;
    asm("mov.b64 {%0, %1}, %2;" : "=f"(r.x), "=f"(r.y) : "l"(v));
    return r;
}

// ----------------------------- fused rope -----------------------------------
// blocks [0,3072): q-rope; [3072,3328): kv-rope
// loc bases: seg0: 12304 both; seg1: w0->2048, w1->4112; seg2: w0->4112, w1->2048
__global__ void rope_all_kernel(const float* __restrict__ cosn,
                                const float* __restrict__ sinn) {
    int d = threadIdx.x;
    int b = blockIdx.x;
    if (b < 3072) {
        int qi = b & 15;
        int h  = (b >> 4) & 31;
        int w  = (b >> 9) & 1;
        int seg = b >> 10;
        int base = (seg == 0) ? 12304 : (seg == 1) ? ((w == 0) ? 2048 : 4112)
                                                   : ((w == 0) ? 4112 : 2048);
        int j = d & 63;
        double inv = exp(-(double)j * 0.14391156831212787);   // ln(10000)/64
        float invf = (float)inv;
        float angf = (float)(base + qi) * invf;               // f32 rounding like ref
        double ang = (double)angf;
        float c = (float)cos(ang), s = (float)sin(ang);
        int t = w * 16 + qi;
        float qv  = g_qkv[t * 6144 + h * 128 + d];
        float rot = (d < 64) ? -g_qkv[t * 6144 + h * 128 + d + 64]
                             :  g_qkv[t * 6144 + h * 128 + d - 64];
        float r = qv * c + rot * s;
        size_t o = ((size_t)((seg * 2 + w) * 8 + (h >> 2))) * 8192
                 + (size_t)d * 64 + ((h & 3) * 16 + qi);
        g_rqt[o] = r;
    } else {
        int bb = b - 3072;
        int qi = bb & 15;
        int kv = (bb >> 4) & 7;
        int w  = bb >> 7;
        int t = w * 16 + qi;
        float c = cosn[(w * 16 + qi) * 128 + d];
        float s = sinn[(w * 16 + qi) * 128 + d];
        float k   = g_qkv[t * 6144 + 4096 + kv * 128 + d];
        float rot = (d < 64) ? -g_qkv[t * 6144 + 4096 + kv * 128 + d + 64]
                             :  g_qkv[t * 6144 + 4096 + kv * 128 + d - 64];
        int o = ((w * 8 + kv) * 16 + qi) * 128 + d;
        g_knew[o] = k * c + rot * s;
        g_vnew[o] = g_qkv[t * 6144 + 5120 + kv * 128 + d];
    }
}

// ----------------------------- GEMM body ------------------------------------
__device__ __forceinline__ void gemm_body(
    const float* __restrict__ A, const float* __restrict__ W,
    float* __restrict__ Cp, int ldC, int colOff, int K, int KC, int o0) {
    __shared__ float As[64][34];
    __shared__ float Ws[64][132];

    int tid = threadIdx.x;
    int kb  = blockIdx.y * KC;
    int to  = tid & 31;
    int tt  = tid >> 5;

    ull c2[4][2];
#pragma unroll
    for (int i = 0; i < 4; i++) { c2[i][0] = 0ULL; c2[i][1] = 0ULL; }

    for (int kk = 0; kk < KC; kk += 64) {
#pragma unroll
        for (int r = 0; r < 2; r++) {
            int f = tid + r * 256;
            int t = f & 31, kq = f >> 5;
            float4 av = *(const float4*)&A[(size_t)t * K + kb + kk + 4 * kq];
            As[4 * kq + 0][t] = av.x;
            As[4 * kq + 1][t] = av.y;
            As[4 * kq + 2][t] = av.z;
            As[4 * kq + 3][t] = av.w;
        }
#pragma unroll
        for (int r = 0; r < 8; r++) {
            int f = tid + r * 256;
            int o = f & 127, kq = f >> 7;
            float4 wv = *(const float4*)&W[(size_t)(o0 + o) * K + kb + kk + 4 * kq];
            Ws[4 * kq + 0][o] = wv.x;
            Ws[4 * kq + 1][o] = wv.y;
            Ws[4 * kq + 2][o] = wv.z;
            Ws[4 * kq + 3][o] = wv.w;
        }
        __syncthreads();
#pragma unroll 8
        for (int k = 0; k < 64; k++) {
            ull a0 = *(const ull*)&As[k][4 * tt];
            ull a1 = *(const ull*)&As[k][4 * tt + 2];
            float4 wv = *(const float4*)&Ws[k][4 * to];
            ull w0 = pk2(wv.x, wv.x), w1 = pk2(wv.y, wv.y);
            ull w2 = pk2(wv.z, wv.z), w3 = pk2(wv.w, wv.w);
            c2[0][0] = ffma2(w0, a0, c2[0][0]); c2[0][1] = ffma2(w0, a1, c2[0][1]);
            c2[1][0] = ffma2(w1, a0, c2[1][0]); c2[1][1] = ffma2(w1, a1, c2[1][1]);
            c2[2][0] = ffma2(w2, a0, c2[2][0]); c2[2][1] = ffma2(w2, a1, c2[2][1]);
            c2[3][0] = ffma2(w3, a0, c2[3][0]); c2[3][1] = ffma2(w3, a1, c2[3][1]);
        }
        __syncthreads();
    }
    int ks = blockIdx.y;
#pragma unroll
    for (int i = 0; i < 4; i++) {
        int o = o0 + 4 * to + i;
#pragma unroll
        for (int p = 0; p < 2; p++) {
            float2 v = unpk(c2[i][p]);
            int t0 = 4 * tt + 2 * p;
            Cp[(size_t)(ks * 32 + t0) * ldC + colOff + o]     = v.x;
            Cp[(size_t)(ks * 32 + t0 + 1) * ldC + colOff + o] = v.y;
        }
    }
}

__global__ __launch_bounds__(256) void qkv_gemm_kernel(
    const float* __restrict__ A, const float* __restrict__ Wq,
    const float* __restrict__ Wk, const float* __restrict__ Wv) {
    int bx = blockIdx.x;
    const float* W; int o0, colOff;
    if (bx < 32)      { W = Wq; o0 = bx * 128;        colOff = 0;    }
    else if (bx < 40) { W = Wk; o0 = (bx - 32) * 128; colOff = 4096; }
    else              { W = Wv; o0 = (bx - 40) * 128; colOff = 5120; }
    gemm_body(A, W, g_qkvp, 6144, colOff, 4096, 256, o0);
}

__global__ __launch_bounds__(256) void o_gemm_kernel(const float* __restrict__ Wo) {
    gemm_body(g_attn, Wo, g_op, 4096, 0, 4096, 256, blockIdx.x * 128);
}

__global__ void reduce_qkv_kernel(const float* __restrict__ bq,
                                  const float* __restrict__ bk,
                                  const float* __restrict__ bv) {
    int idx = blockIdx.x * 256 + threadIdx.x;   // < 196608
    float s = 0.f;
#pragma unroll
    for (int ks = 0; ks < 16; ks++) s += g_qkvp[(size_t)ks * 196608 + idx];
    int o = idx % 6144;
    float b = (o < 4096) ? bq[o] : (o < 5120 ? bk[o - 4096] : bv[o - 5120]);
    g_qkv[idx] = s + b;
}

__global__ void reduce_out_kernel(float* __restrict__ out) {
    int idx = blockIdx.x * 256 + threadIdx.x;   // < 131072
    float s = 0.f;
#pragma unroll
    for (int ks = 0; ks < 16; ks++) s += g_op[(size_t)ks * 131072 + idx];
    out[idx] = s;
}

// ----------------------------- attention ------------------------------------
// grid (98, 16=w*8+kv), 512 threads (16 warps = 4 heads x 4 q-quarters).
// smem: KT [0,16896) rows d stride 132 (later V rows l stride 132)
//       SCt [16896,25600) rows key stride 68 (score[key][hq])
//       RQt [25600,34304) rows d stride 68 (rq[d][hq], non-dup)
__global__ __launch_bounds__(512) void attn_kernel(
    const float* __restrict__ ssk, const float* __restrict__ ssv,
    const float* __restrict__ w0k, const float* __restrict__ w0v,
    const float* __restrict__ w1k, const float* __restrict__ w1v) {
    extern __shared__ float sm[];
    float* KT  = sm;
    float* SCt = sm + 16896;
    float* RQt = sm + 25600;
    __shared__ float redm[64][8], redl[64][8], mfin[64];

    int tid = threadIdx.x;
    int cid = blockIdx.x, wkv = blockIdx.y;
    int w = wkv >> 3, kv = wkv & 7;

    int seg, nl = 128, ownnew = 0;
    const float *ksrc, *vsrc;
    if (cid < 64) {
        seg = 0;
        size_t off = ((size_t)kv * 8192 + cid * 128) * 128;
        ksrc = ssk + off; vsrc = ssv + off;
    } else if (cid < 81) {
        seg = 1;
        int cc = cid - 64;
        if (cc < 16) {
            size_t off = ((size_t)kv * 2048 + cc * 128) * 128;
            ksrc = w0k + off; vsrc = w0v + off;
        } else {
            nl = 16; ownnew = (w == 0);
            size_t off = (size_t)kv * 16 * 128;
            ksrc = g_knew + off; vsrc = g_vnew + off;
        }
    } else {
        seg = 2;
        int cc = cid - 81;
        if (cc < 16) {
            size_t off = ((size_t)kv * 2048 + cc * 128) * 128;
            ksrc = w1k + off; vsrc = w1v + off;
        } else {
            nl = 16; ownnew = (w == 1);
            size_t off = (size_t)(8 + kv) * 16 * 128;
            ksrc = g_knew + off; vsrc = g_vnew + off;
        }
    }
    int pidx = wkv * 98 + cid;

    // ---- stage RQt[d][hq] (non-dup, 8192 floats) ----
    {
        const float4* s4 = (const float4*)(g_rqt + (size_t)((seg * 2 + w) * 8 + kv) * 8192);
#pragma unroll
        for (int r = 0; r < 4; r++) {
            int i = tid + r * 512;            // float4 index, [0,2048)
            int d = i >> 4, c = i & 15;
            *(float4*)&RQt[d * 68 + 4 * c] = s4[i];
        }
    }
    // ---- stage K transposed: KT[d][key], stride 132 ----
#pragma unroll
    for (int r = 0; r < 8; r++) {
        int f = tid + r * 512;
        int key = f & 127, dq = f >> 7;      // dq: 4-dim group 0..31
        float4 v = (key < nl) ? ((const float4*)ksrc)[key * 32 + dq]
                              : make_float4(0.f, 0.f, 0.f, 0.f);
        KT[(4 * dq + 0) * 132 + key] = v.x;
        KT[(4 * dq + 1) * 132 + key] = v.y;
        KT[(4 * dq + 2) * 132 + key] = v.z;
        KT[(4 * dq + 3) * 132 + key] = v.w;
    }
    __syncthreads();

    int lane = tid & 31, wi = tid >> 5;
    int hh = wi & 3, q0 = (wi >> 2) * 4;     // head, q-quarter
    int hq0 = hh * 16 + q0;

    // ---- QK: acc[qp][j] = score pairs (q0+2qp, q0+2qp+1) x key (lane+32j) ----
    {
        ull acc[2][4];
#pragma unroll
        for (int a = 0; a < 2; a++)
#pragma unroll
            for (int b = 0; b < 4; b++) acc[a][b] = 0ULL;
#pragma unroll 4
        for (int d = 0; d < 128; d++) {
            ulonglong2 ra = *(const ulonglong2*)&RQt[d * 68 + hq0];
            float k0 = KT[d * 132 + lane];
            float k1 = KT[d * 132 + lane + 32];
            float k2 = KT[d * 132 + lane + 64];
            float k3 = KT[d * 132 + lane + 96];
            ull p0 = pk2(k0, k0), p1 = pk2(k1, k1);
            ull p2 = pk2(k2, k2), p3 = pk2(k3, k3);
            acc[0][0] = ffma2(ra.x, p0, acc[0][0]);
            acc[0][1] = ffma2(ra.x, p1, acc[0][1]);
            acc[0][2] = ffma2(ra.x, p2, acc[0][2]);
            acc[0][3] = ffma2(ra.x, p3, acc[0][3]);
            acc[1][0] = ffma2(ra.y, p0, acc[1][0]);
            acc[1][1] = ffma2(ra.y, p1, acc[1][1]);
            acc[1][2] = ffma2(ra.y, p2, acc[1][2]);
            acc[1][3] = ffma2(ra.y, p3, acc[1][3]);
        }
#pragma unroll
        for (int qp = 0; qp < 2; qp++) {
            int qa = q0 + 2 * qp;
#pragma unroll
            for (int j = 0; j < 4; j++) {
                int key = lane + 32 * j;
                float2 s = unpk(acc[qp][j]);
                bool vis = key < nl;
                float e0 = (vis && (!ownnew || key <= qa))     ? s.x * SCALE : -1e30f;
                float e1 = (vis && (!ownnew || key <= qa + 1)) ? s.y * SCALE : -1e30f;
                *(float2*)&SCt[key * 68 + hh * 16 + qa] = make_float2(e0, e1);
            }
        }
    }
    __syncthreads();

    // ---- stage V (reuse KT region): V[l][dim], stride 132 ----
#pragma unroll
    for (int r = 0; r < 8; r++) {
        int f = tid + r * 512;
        int l = f >> 5, dq = f & 31;
        float4 v = (l < nl) ? ((const float4*)vsrc)[l * 32 + dq]
                            : make_float4(0.f, 0.f, 0.f, 0.f);
        *(float4*)&KT[l * 132 + 4 * dq] = v;
    }

    // ---- per-chunk softmax on SCt columns (8 parts x 16 keys) ----
    {
        int hq = tid & 63, part = tid >> 6;
        float m = -1e30f;
#pragma unroll
        for (int i = 0; i < 16; i++)
            m = fmaxf(m, SCt[(part * 16 + i) * 68 + hq]);
        redm[hq][part] = m;
        __syncthreads();
        if (tid < 64) {
            float mm = redm[tid][0];
#pragma unroll
            for (int p = 1; p < 8; p++) mm = fmaxf(mm, redm[tid][p]);
            mfin[tid] = mm;
        }
        __syncthreads();
        float mm = mfin[hq];
        float s = 0.f;
#pragma unroll
        for (int i = 0; i < 16; i++) {
            int idx = (part * 16 + i) * 68 + hq;
            float p = __expf(SCt[idx] - mm);
            SCt[idx] = p;
            s += p;
        }
        redl[hq][part] = s;
        __syncthreads();
        if (tid < 64) {
            float L = 0.f;
#pragma unroll
            for (int p = 0; p < 8; p++) L += redl[tid][p];
            g_pm[(size_t)pidx * 64 + tid] = mfin[tid];
            g_pl[(size_t)pidx * 64 + tid] = L;
        }
        __syncthreads();   // probs + V both ready
    }

    // ---- PV: acc[qp][j] = out pairs (q,q+1) x dim (lane+32j) ----
    {
        ull acc[2][4];
#pragma unroll
        for (int a = 0; a < 2; a++)
#pragma unroll
            for (int b = 0; b < 4; b++) acc[a][b] = 0ULL;
#pragma unroll 4
        for (int l = 0; l < 128; l++) {
            ulonglong2 ra = *(const ulonglong2*)&SCt[l * 68 + hq0];
            float v0 = KT[l * 132 + lane];
            float v1 = KT[l * 132 + lane + 32];
            float v2 = KT[l * 132 + lane + 64];
            float v3 = KT[l * 132 + lane + 96];
            ull p0 = pk2(v0, v0), p1 = pk2(v1, v1);
            ull p2 = pk2(v2, v2), p3 = pk2(v3, v3);
            acc[0][0] = ffma2(ra.x, p0, acc[0][0]);
            acc[0][1] = ffma2(ra.x, p1, acc[0][1]);
            acc[0][2] = ffma2(ra.x, p2, acc[0][2]);
            acc[0][3] = ffma2(ra.x, p3, acc[0][3]);
            acc[1][0] = ffma2(ra.y, p0, acc[1][0]);
            acc[1][1] = ffma2(ra.y, p1, acc[1][1]);
            acc[1][2] = ffma2(ra.y, p2, acc[1][2]);
            acc[1][3] = ffma2(ra.y, p3, acc[1][3]);
        }
#pragma unroll
        for (int qp = 0; qp < 2; qp++) {
            int hqa = hq0 + 2 * qp;
#pragma unroll
            for (int j = 0; j < 4; j++) {
                int dim = lane + 32 * j;
                float2 a = unpk(acc[qp][j]);
                g_pacc[((size_t)pidx * 64 + hqa) * 128 + dim]     = a.x;
                g_pacc[((size_t)pidx * 64 + hqa + 1) * 128 + dim] = a.y;
            }
        }
    }
}

// split-K combine: grid 1024 = (w,h,q), 128 threads
__global__ __launch_bounds__(128) void combine_kernel() {
    __shared__ float swgt[98];
    __shared__ float redA[4], redB[4];
    int b = blockIdx.x;
    int q = b & 15, h = (b >> 4) & 31, w = b >> 9;
    int kv = h >> 2;
    int hq = (h & 3) * 16 + q;
    size_t base = (size_t)(w * 8 + kv) * 98;
    int tid = threadIdx.x;

    float pm = (tid < 98) ? g_pm[(base + tid) * 64 + hq] : -3e38f;
    float pl = (tid < 98) ? g_pl[(base + tid) * 64 + hq] : 0.f;
    float m = pm;
#pragma unroll
    for (int o = 16; o; o >>= 1) m = fmaxf(m, __shfl_xor_sync(0xffffffffu, m, o));
    if ((tid & 31) == 0) redA[tid >> 5] = m;
    __syncthreads();
    float M = fmaxf(fmaxf(redA[0], redA[1]), fmaxf(redA[2], redA[3]));
    float wgt = __expf(pm - M);
    if (tid < 98) swgt[tid] = wgt;
    float l = (tid < 98) ? pl * wgt : 0.f;
#pragma unroll
    for (int o = 16; o; o >>= 1) l += __shfl_xor_sync(0xffffffffu, l, o);
    if ((tid & 31) == 0) redB[tid >> 5] = l;
    __syncthreads();
    float L = redB[0] + redB[1] + redB[2] + redB[3];

    float A = 0.f;
#pragma unroll 7
    for (int c = 0; c < 98; c++)
        A += g_pacc[((base + c) * 64 + hq) * 128 + tid] * swgt[c];
    int t = w * 16 + q;
    g_attn[(size_t)t * 4096 + h * 128 + tid] = A / L;
}

// ----------------------------- launch ---------------------------------------
extern "C" void kernel_launch(void* const* d_in, const int* in_sizes, int n_in,
                              void* d_out, int out_size) {
    const float* hs   = (const float*)d_in[0];
    const float* Wq   = (const float*)d_in[1];
    const float* bq   = (const float*)d_in[2];
    const float* Wk   = (const float*)d_in[3];
    const float* bk   = (const float*)d_in[4];
    const float* Wv   = (const float*)d_in[5];
    const float* bv   = (const float*)d_in[6];
    const float* Wo   = (const float*)d_in[7];
    const float* ssk  = (const float*)d_in[8];
    const float* ssv  = (const float*)d_in[9];
    const float* w0k  = (const float*)d_in[10];
    const float* w0v  = (const float*)d_in[11];
    const float* w1k  = (const float*)d_in[12];
    const float* w1v  = (const float*)d_in[13];
    const float* cosn = (const float*)d_in[14];
    const float* sinn = (const float*)d_in[15];
    float* out = (float*)d_out;

    cudaFuncSetAttribute(attn_kernel,
                         cudaFuncAttributeMaxDynamicSharedMemorySize, 137216);

    qkv_gemm_kernel<<<dim3(48, 16), 256>>>(hs, Wq, Wk, Wv);
    reduce_qkv_kernel<<<768, 256>>>(bq, bk, bv);
    rope_all_kernel<<<3328, 128>>>(cosn, sinn);

    attn_kernel<<<dim3(98, 16), 512, 137216>>>(ssk, ssv, w0k, w0v, w1k, w1v);
    combine_kernel<<<1024, 128>>>();

    o_gemm_kernel<<<dim3(32, 16), 256>>>(Wo);
    reduce_out_kernel<<<512, 256>>>(out);
}

// round 17
// speedup vs baseline: 1.1143x; 1.1143x over previous
#include <cuda_runtime.h>
#include <cuda_bf16.h>
#include <math.h>

typedef unsigned long long ull;

#define SCALE 0.08838834764831843f

// ----------------------------- device scratch -------------------------------
__device__ float  g_qkvp[16 * 32 * 6144];         // k-split partials (QKV)
__device__ float  g_qkv [32 * 6144];              // reduced qkv + bias
__device__ float  g_rqt [48 * 128 * 64];          // roped q, transposed [set][d][hq]
__device__ float  g_knew[2 * 8 * 16 * 128];       // roped new keys
__device__ float  g_vnew[2 * 8 * 16 * 128];       // new values
__device__ float  g_pm [16 * 98 * 64];            // split-K partial max
__device__ float  g_pl [16 * 98 * 64];            // split-K partial sum
__device__ float  g_pacc[16 * 98 * 64 * 128];     // split-K partial accum
__device__ float  g_attn[32 * 4096];              // attention out, tokens x (H*D)
__device__ float  g_op [16 * 32 * 4096];          // k-split partials (O proj)

// ----------------------------- f32x2 helpers --------------------------------
__device__ __forceinline__ ull ffma2(ull a, ull b, ull c) {
    ull d;
    asm("fma.rn.f32x2 %0, %1, %2, %3;" : "=l"(d) : "l"(a), "l"(b), "l"(c));
    return d;
}
__device__ __forceinline__ ull pk2(float x, float y) {
    ull r;
    asm("mov.b64 %0, {%1, %2};" : "=l"(r) : "f"(x), "f"(y));
    return r;
}
__device__ __forceinline__ float2 unpk(ull v) {
    float2 r;
    asm("mov.b64 {%0, %1}, %2;" : "=f"(r.x), "=f"(r.y) : "l"(v));
    return r;
}

// ----------------------------- fused rope -----------------------------------
// blocks [0,3072): q-rope; [3072,3328): kv-rope
// loc bases: seg0: 12304 both; seg1: w0->2048, w1->4112; seg2: w0->4112, w1->2048
__global__ void rope_all_kernel(const float* __restrict__ cosn,
                                const float* __restrict__ sinn) {
    int d = threadIdx.x;
    int b = blockIdx.x;
    if (b < 3072) {
        int qi = b & 15;
        int h  = (b >> 4) & 31;
        int w  = (b >> 9) & 1;
        int seg = b >> 10;
        int base = (seg == 0) ? 12304 : (seg == 1) ? ((w == 0) ? 2048 : 4112)
                                                   : ((w == 0) ? 4112 : 2048);
        int j = d & 63;
        double inv = exp(-(double)j * 0.14391156831212787);   // ln(10000)/64
        float invf = (float)inv;
        float angf = (float)(base + qi) * invf;               // f32 rounding like ref
        double ang = (double)angf;
        float c = (float)cos(ang), s = (float)sin(ang);
        int t = w * 16 + qi;
        float qv  = g_qkv[t * 6144 + h * 128 + d];
        float rot = (d < 64) ? -g_qkv[t * 6144 + h * 128 + d + 64]
                             :  g_qkv[t * 6144 + h * 128 + d - 64];
        float r = qv * c + rot * s;
        size_t o = ((size_t)((seg * 2 + w) * 8 + (h >> 2))) * 8192
                 + (size_t)d * 64 + ((h & 3) * 16 + qi);
        g_rqt[o] = r;
    } else {
        int bb = b - 3072;
        int qi = bb & 15;
        int kv = (bb >> 4) & 7;
        int w  = bb >> 7;
        int t = w * 16 + qi;
        float c = cosn[(w * 16 + qi) * 128 + d];
        float s = sinn[(w * 16 + qi) * 128 + d];
        float k   = g_qkv[t * 6144 + 4096 + kv * 128 + d];
        float rot = (d < 64) ? -g_qkv[t * 6144 + 4096 + kv * 128 + d + 64]
                             :  g_qkv[t * 6144 + 4096 + kv * 128 + d - 64];
        int o = ((w * 8 + kv) * 16 + qi) * 128 + d;
        g_knew[o] = k * c + rot * s;
        g_vnew[o] = g_qkv[t * 6144 + 5120 + kv * 128 + d];
    }
}

// ----------------------------- GEMM body (coalesced) -------------------------
// C[t][o] = sum_k A[t][k]*W[o][k]; k-split partials per blockIdx.y.
// A tile staged As[k][t] (stride 34); W tile staged Wt[o][k] (stride 65, scalar
// stores -- odd stride keeps compute reads conflict-free but forbids STS.128).
// LDG: 16 lanes cover one row's contiguous 256B (fully coalesced).
__device__ __forceinline__ void gemm_body(
    const float* __restrict__ A, const float* __restrict__ W,
    float* __restrict__ Cp, int ldC, int colOff, int K, int KC, int o0) {
    __shared__ float As[64][34];      // [k][t]
    __shared__ float Wt[128 * 65];    // [o][k] stride 65

    int tid = threadIdx.x;
    int kb  = blockIdx.y * KC;
    int to  = tid & 31;
    int tt  = tid >> 5;

    ull c2[4][2];
#pragma unroll
    for (int i = 0; i < 4; i++) { c2[i][0] = 0ULL; c2[i][1] = 0ULL; }

    for (int kk = 0; kk < KC; kk += 64) {
        // A tile: 32t x 64k, coalesced (c = k-group, t = row)
#pragma unroll
        for (int r = 0; r < 2; r++) {
            int f = tid + r * 256;            // [0,512)
            int c = f & 15, t = f >> 4;
            float4 av = *(const float4*)&A[(size_t)t * K + kb + kk + 4 * c];
            As[4 * c + 0][t] = av.x;
            As[4 * c + 1][t] = av.y;
            As[4 * c + 2][t] = av.z;
            As[4 * c + 3][t] = av.w;
        }
        // W tile: 128o x 64k, coalesced LDG; scalar STS into [o][k] stride 65
#pragma unroll
        for (int r = 0; r < 8; r++) {
            int f = tid + r * 256;            // [0,2048)
            int c = f & 15, o = f >> 4;
            float4 wv = *(const float4*)&W[(size_t)(o0 + o) * K + kb + kk + 4 * c];
            float* p = &Wt[o * 65 + 4 * c];
            p[0] = wv.x;
            p[1] = wv.y;
            p[2] = wv.z;
            p[3] = wv.w;
        }
        __syncthreads();
#pragma unroll 8
        for (int k = 0; k < 64; k++) {
            ull a0 = *(const ull*)&As[k][4 * tt];       // t-pair (4tt,4tt+1), bcast
            ull a1 = *(const ull*)&As[k][4 * tt + 2];   // (4tt+2,4tt+3), bcast
            float w0 = Wt[(to      ) * 65 + k];         // conflict-free LDS.32
            float w1 = Wt[(to + 32 ) * 65 + k];
            float w2 = Wt[(to + 64 ) * 65 + k];
            float w3 = Wt[(to + 96 ) * 65 + k];
            ull p0 = pk2(w0, w0), p1 = pk2(w1, w1);
            ull p2 = pk2(w2, w2), p3 = pk2(w3, w3);
            c2[0][0] = ffma2(p0, a0, c2[0][0]); c2[0][1] = ffma2(p0, a1, c2[0][1]);
            c2[1][0] = ffma2(p1, a0, c2[1][0]); c2[1][1] = ffma2(p1, a1, c2[1][1]);
            c2[2][0] = ffma2(p2, a0, c2[2][0]); c2[2][1] = ffma2(p2, a1, c2[2][1]);
            c2[3][0] = ffma2(p3, a0, c2[3][0]); c2[3][1] = ffma2(p3, a1, c2[3][1]);
        }
        __syncthreads();
    }
    int ks = blockIdx.y;
#pragma unroll
    for (int j = 0; j < 4; j++) {
        int o = o0 + to + 32 * j;
#pragma unroll
        for (int p = 0; p < 2; p++) {
            float2 v = unpk(c2[j][p]);
            int t0 = 4 * tt + 2 * p;
            Cp[(size_t)(ks * 32 + t0) * ldC + colOff + o]     = v.x;
            Cp[(size_t)(ks * 32 + t0 + 1) * ldC + colOff + o] = v.y;
        }
    }
}

__global__ __launch_bounds__(256) void qkv_gemm_kernel(
    const float* __restrict__ A, const float* __restrict__ Wq,
    const float* __restrict__ Wk, const float* __restrict__ Wv) {
    int bx = blockIdx.x;
    const float* W; int o0, colOff;
    if (bx < 32)      { W = Wq; o0 = bx * 128;        colOff = 0;    }
    else if (bx < 40) { W = Wk; o0 = (bx - 32) * 128; colOff = 4096; }
    else              { W = Wv; o0 = (bx - 40) * 128; colOff = 5120; }
    gemm_body(A, W, g_qkvp, 6144, colOff, 4096, 256, o0);
}

__global__ __launch_bounds__(256) void o_gemm_kernel(const float* __restrict__ Wo) {
    gemm_body(g_attn, Wo, g_op, 4096, 0, 4096, 256, blockIdx.x * 128);
}

__global__ void reduce_qkv_kernel(const float* __restrict__ bq,
                                  const float* __restrict__ bk,
                                  const float* __restrict__ bv) {
    int idx = blockIdx.x * 256 + threadIdx.x;   // < 196608
    float s = 0.f;
#pragma unroll
    for (int ks = 0; ks < 16; ks++) s += g_qkvp[(size_t)ks * 196608 + idx];
    int o = idx % 6144;
    float b = (o < 4096) ? bq[o] : (o < 5120 ? bk[o - 4096] : bv[o - 5120]);
    g_qkv[idx] = s + b;
}

__global__ void reduce_out_kernel(float* __restrict__ out) {
    int idx = blockIdx.x * 256 + threadIdx.x;   // < 131072
    float s = 0.f;
#pragma unroll
    for (int ks = 0; ks < 16; ks++) s += g_op[(size_t)ks * 131072 + idx];
    out[idx] = s;
}

// ----------------------------- attention ------------------------------------
// grid (98, 16=w*8+kv), 512 threads (16 warps = 4 heads x 4 q-quarters).
// smem: KT [0,16896) rows d stride 132 (later V rows l stride 132)
//       SCt [16896,25600) rows key stride 68 (score[key][hq])
//       RQt [25600,34304) rows d stride 68 (rq[d][hq], non-dup)
__global__ __launch_bounds__(512) void attn_kernel(
    const float* __restrict__ ssk, const float* __restrict__ ssv,
    const float* __restrict__ w0k, const float* __restrict__ w0v,
    const float* __restrict__ w1k, const float* __restrict__ w1v) {
    extern __shared__ float sm[];
    float* KT  = sm;
    float* SCt = sm + 16896;
    float* RQt = sm + 25600;
    __shared__ float redm[64][8], redl[64][8], mfin[64];

    int tid = threadIdx.x;
    int cid = blockIdx.x, wkv = blockIdx.y;
    int w = wkv >> 3, kv = wkv & 7;

    int seg, nl = 128, ownnew = 0;
    const float *ksrc, *vsrc;
    if (cid < 64) {
        seg = 0;
        size_t off = ((size_t)kv * 8192 + cid * 128) * 128;
        ksrc = ssk + off; vsrc = ssv + off;
    } else if (cid < 81) {
        seg = 1;
        int cc = cid - 64;
        if (cc < 16) {
            size_t off = ((size_t)kv * 2048 + cc * 128) * 128;
            ksrc = w0k + off; vsrc = w0v + off;
        } else {
            nl = 16; ownnew = (w == 0);
            size_t off = (size_t)kv * 16 * 128;
            ksrc = g_knew + off; vsrc = g_vnew + off;
        }
    } else {
        seg = 2;
        int cc = cid - 81;
        if (cc < 16) {
            size_t off = ((size_t)kv * 2048 + cc * 128) * 128;
            ksrc = w1k + off; vsrc = w1v + off;
        } else {
            nl = 16; ownnew = (w == 1);
            size_t off = (size_t)(8 + kv) * 16 * 128;
            ksrc = g_knew + off; vsrc = g_vnew + off;
        }
    }
    int pidx = wkv * 98 + cid;

    // ---- stage RQt[d][hq] (non-dup, 8192 floats) ----
    {
        const float4* s4 = (const float4*)(g_rqt + (size_t)((seg * 2 + w) * 8 + kv) * 8192);
#pragma unroll
        for (int r = 0; r < 4; r++) {
            int i = tid + r * 512;            // float4 index, [0,2048)
            int d = i >> 4, c = i & 15;
            *(float4*)&RQt[d * 68 + 4 * c] = s4[i];
        }
    }
    // ---- stage K transposed: KT[d][key], stride 132 ----
#pragma unroll
    for (int r = 0; r < 8; r++) {
        int f = tid + r * 512;
        int key = f & 127, dq = f >> 7;      // dq: 4-dim group 0..31
        float4 v = (key < nl) ? ((const float4*)ksrc)[key * 32 + dq]
                              : make_float4(0.f, 0.f, 0.f, 0.f);
        KT[(4 * dq + 0) * 132 + key] = v.x;
        KT[(4 * dq + 1) * 132 + key] = v.y;
        KT[(4 * dq + 2) * 132 + key] = v.z;
        KT[(4 * dq + 3) * 132 + key] = v.w;
    }
    __syncthreads();

    int lane = tid & 31, wi = tid >> 5;
    int hh = wi & 3, q0 = (wi >> 2) * 4;     // head, q-quarter
    int hq0 = hh * 16 + q0;

    // ---- QK: acc[qp][j] = score pairs (q0+2qp, q0+2qp+1) x key (lane+32j) ----
    {
        ull acc[2][4];
#pragma unroll
        for (int a = 0; a < 2; a++)
#pragma unroll
            for (int b = 0; b < 4; b++) acc[a][b] = 0ULL;
#pragma unroll 4
        for (int d = 0; d < 128; d++) {
            ulonglong2 ra = *(const ulonglong2*)&RQt[d * 68 + hq0];
            float k0 = KT[d * 132 + lane];
            float k1 = KT[d * 132 + lane + 32];
            float k2 = KT[d * 132 + lane + 64];
            float k3 = KT[d * 132 + lane + 96];
            ull p0 = pk2(k0, k0), p1 = pk2(k1, k1);
            ull p2 = pk2(k2, k2), p3 = pk2(k3, k3);
            acc[0][0] = ffma2(ra.x, p0, acc[0][0]);
            acc[0][1] = ffma2(ra.x, p1, acc[0][1]);
            acc[0][2] = ffma2(ra.x, p2, acc[0][2]);
            acc[0][3] = ffma2(ra.x, p3, acc[0][3]);
            acc[1][0] = ffma2(ra.y, p0, acc[1][0]);
            acc[1][1] = ffma2(ra.y, p1, acc[1][1]);
            acc[1][2] = ffma2(ra.y, p2, acc[1][2]);
            acc[1][3] = ffma2(ra.y, p3, acc[1][3]);
        }
#pragma unroll
        for (int qp = 0; qp < 2; qp++) {
            int qa = q0 + 2 * qp;
#pragma unroll
            for (int j = 0; j < 4; j++) {
                int key = lane + 32 * j;
                float2 s = unpk(acc[qp][j]);
                bool vis = key < nl;
                float e0 = (vis && (!ownnew || key <= qa))     ? s.x * SCALE : -1e30f;
                float e1 = (vis && (!ownnew || key <= qa + 1)) ? s.y * SCALE : -1e30f;
                *(float2*)&SCt[key * 68 + hh * 16 + qa] = make_float2(e0, e1);
            }
        }
    }
    __syncthreads();

    // ---- stage V (reuse KT region): V[l][dim], stride 132 ----
#pragma unroll
    for (int r = 0; r < 8; r++) {
        int f = tid + r * 512;
        int l = f >> 5, dq = f & 31;
        float4 v = (l < nl) ? ((const float4*)vsrc)[l * 32 + dq]
                            : make_float4(0.f, 0.f, 0.f, 0.f);
        *(float4*)&KT[l * 132 + 4 * dq] = v;
    }

    // ---- per-chunk softmax on SCt columns (8 parts x 16 keys) ----
    {
        int hq = tid & 63, part = tid >> 6;
        float m = -1e30f;
#pragma unroll
        for (int i = 0; i < 16; i++)
            m = fmaxf(m, SCt[(part * 16 + i) * 68 + hq]);
        redm[hq][part] = m;
        __syncthreads();
        if (tid < 64) {
            float mm = redm[tid][0];
#pragma unroll
            for (int p = 1; p < 8; p++) mm = fmaxf(mm, redm[tid][p]);
            mfin[tid] = mm;
        }
        __syncthreads();
        float mm = mfin[hq];
        float s = 0.f;
#pragma unroll
        for (int i = 0; i < 16; i++) {
            int idx = (part * 16 + i) * 68 + hq;
            float p = __expf(SCt[idx] - mm);
            SCt[idx] = p;
            s += p;
        }
        redl[hq][part] = s;
        __syncthreads();
        if (tid < 64) {
            float L = 0.f;
#pragma unroll
            for (int p = 0; p < 8; p++) L += redl[tid][p];
            g_pm[(size_t)pidx * 64 + tid] = mfin[tid];
            g_pl[(size_t)pidx * 64 + tid] = L;
        }
        __syncthreads();   // probs + V both ready
    }

    // ---- PV: acc[qp][j] = out pairs (q,q+1) x dim (lane+32j) ----
    {
        ull acc[2][4];
#pragma unroll
        for (int a = 0; a < 2; a++)
#pragma unroll
            for (int b = 0; b < 4; b++) acc[a][b] = 0ULL;
#pragma unroll 4
        for (int l = 0; l < 128; l++) {
            ulonglong2 ra = *(const ulonglong2*)&SCt[l * 68 + hq0];
            float v0 = KT[l * 132 + lane];
            float v1 = KT[l * 132 + lane + 32];
            float v2 = KT[l * 132 + lane + 64];
            float v3 = KT[l * 132 + lane + 96];
            ull p0 = pk2(v0, v0), p1 = pk2(v1, v1);
            ull p2 = pk2(v2, v2), p3 = pk2(v3, v3);
            acc[0][0] = ffma2(ra.x, p0, acc[0][0]);
            acc[0][1] = ffma2(ra.x, p1, acc[0][1]);
            acc[0][2] = ffma2(ra.x, p2, acc[0][2]);
            acc[0][3] = ffma2(ra.x, p3, acc[0][3]);
            acc[1][0] = ffma2(ra.y, p0, acc[1][0]);
            acc[1][1] = ffma2(ra.y, p1, acc[1][1]);
            acc[1][2] = ffma2(ra.y, p2, acc[1][2]);
            acc[1][3] = ffma2(ra.y, p3, acc[1][3]);
        }
#pragma unroll
        for (int qp = 0; qp < 2; qp++) {
            int hqa = hq0 + 2 * qp;
#pragma unroll
            for (int j = 0; j < 4; j++) {
                int dim = lane + 32 * j;
                float2 a = unpk(acc[qp][j]);
                g_pacc[((size_t)pidx * 64 + hqa) * 128 + dim]     = a.x;
                g_pacc[((size_t)pidx * 64 + hqa + 1) * 128 + dim] = a.y;
            }
        }
    }
}

// split-K combine: grid 1024 = (w,h,q), 128 threads
__global__ __launch_bounds__(128) void combine_kernel() {
    __shared__ float swgt[98];
    __shared__ float redA[4], redB[4];
    int b = blockIdx.x;
    int q = b & 15, h = (b >> 4) & 31, w = b >> 9;
    int kv = h >> 2;
    int hq = (h & 3) * 16 + q;
    size_t base = (size_t)(w * 8 + kv) * 98;
    int tid = threadIdx.x;

    float pm = (tid < 98) ? g_pm[(base + tid) * 64 + hq] : -3e38f;
    float pl = (tid < 98) ? g_pl[(base + tid) * 64 + hq] : 0.f;
    float m = pm;
#pragma unroll
    for (int o = 16; o; o >>= 1) m = fmaxf(m, __shfl_xor_sync(0xffffffffu, m, o));
    if ((tid & 31) == 0) redA[tid >> 5] = m;
    __syncthreads();
    float M = fmaxf(fmaxf(redA[0], redA[1]), fmaxf(redA[2], redA[3]));
    float wgt = __expf(pm - M);
    if (tid < 98) swgt[tid] = wgt;
    float l = (tid < 98) ? pl * wgt : 0.f;
#pragma unroll
    for (int o = 16; o; o >>= 1) l += __shfl_xor_sync(0xffffffffu, l, o);
    if ((tid & 31) == 0) redB[tid >> 5] = l;
    __syncthreads();
    float L = redB[0] + redB[1] + redB[2] + redB[3];

    float A = 0.f;
#pragma unroll 7
    for (int c = 0; c < 98; c++)
        A += g_pacc[((base + c) * 64 + hq) * 128 + tid] * swgt[c];
    int t = w * 16 + q;
    g_attn[(size_t)t * 4096 + h * 128 + tid] = A / L;
}

// ----------------------------- launch ---------------------------------------
extern "C" void kernel_launch(void* const* d_in, const int* in_sizes, int n_in,
                              void* d_out, int out_size) {
    const float* hs   = (const float*)d_in[0];
    const float* Wq   = (const float*)d_in[1];
    const float* bq   = (const float*)d_in[2];
    const float* Wk   = (const float*)d_in[3];
    const float* bk   = (const float*)d_in[4];
    const float* Wv   = (const float*)d_in[5];
    const float* bv   = (const float*)d_in[6];
    const float* Wo   = (const float*)d_in[7];
    const float* ssk  = (const float*)d_in[8];
    const float* ssv  = (const float*)d_in[9];
    const float* w0k  = (const float*)d_in[10];
    const float* w0v  = (const float*)d_in[11];
    const float* w1k  = (const float*)d_in[12];
    const float* w1v  = (const float*)d_in[13];
    const float* cosn = (const float*)d_in[14];
    const float* sinn = (const float*)d_in[15];
    float* out = (float*)d_out;

    cudaFuncSetAttribute(attn_kernel,
                         cudaFuncAttributeMaxDynamicSharedMemorySize, 137216);

    qkv_gemm_kernel<<<dim3(48, 16), 256>>>(hs, Wq, Wk, Wv);
    reduce_qkv_kernel<<<768, 256>>>(bq, bk, bv);
    rope_all_kernel<<<3328, 128>>>(cosn, sinn);

    attn_kernel<<<dim3(98, 16), 512, 137216>>>(ssk, ssv, w0k, w0v, w1k, w1v);
    combine_kernel<<<1024, 128>>>();

    o_gemm_kernel<<<dim3(32, 16), 256>>>(Wo);
    reduce_out_kernel<<<512, 256>>>(out);
}